// round 14
// baseline (speedup 1.0000x reference)
#include <cuda_runtime.h>
#include <cstdint>

#define NHEADS 8
#define HDIM   64
#define QLEN   16
#define HIDDEN 512
#define BLKSZ  16
#define NLOGICAL 2048
#define NSPLIT 128
#define BPS (NLOGICAL / NSPLIT)   // 16 blocks per split
#define ITERS (BPS / 2)           // 8 iterations of 32 keys

typedef unsigned long long ull;

// scratch (no cudaMalloc allowed)
__device__ __align__(16) float g_q [NHEADS * QLEN * HDIM];
__device__ __align__(16) float g_pl[NHEADS * NSPLIT * QLEN];
__device__ __align__(16) float g_po[NHEADS * NSPLIT * QLEN * HDIM];
__device__ __align__(16) float g_ao[QLEN * HIDDEN];
__device__ int g_bt[NLOGICAL];
__device__ int g_cnt;            // reduce->oproj barrier (reset by qproj each replay)

// ---- packed f32x2 helpers --------------------------------------------------
__device__ __forceinline__ ull pk2(float lo, float hi) {
    ull r; asm("mov.b64 %0,{%1,%2};" : "=l"(r) : "f"(lo), "f"(hi)); return r;
}
__device__ __forceinline__ void upk2(ull p, float& lo, float& hi) {
    asm("mov.b64 {%0,%1},%2;" : "=f"(lo), "=f"(hi) : "l"(p));
}
__device__ __forceinline__ ull fma2(ull a, ull b, ull c) {
    ull d; asm("fma.rn.f32x2 %0,%1,%2,%3;" : "=l"(d) : "l"(a), "l"(b), "l"(c)); return d;
}

// ---- cp.async helpers --------------------------------------------------------
__device__ __forceinline__ uint32_t s2u(const void* p) {
    uint32_t a;
    asm("{ .reg .u64 t; cvta.to.shared.u64 t, %1; cvt.u32.u64 %0, t; }" : "=r"(a) : "l"(p));
    return a;
}
__device__ __forceinline__ void cpa16(uint32_t dst, const void* src) {
    asm volatile("cp.async.cg.shared.global [%0], [%1], 16;" :: "r"(dst), "l"(src) : "memory");
}
__device__ __forceinline__ void cpa_commit() {
    asm volatile("cp.async.commit_group;" ::: "memory");
}
__device__ __forceinline__ void cpa_wait0() {
    asm volatile("cp.async.wait_group 0;" ::: "memory");
}

// -----------------------------------------------------------------------------
// Kernel 1: q = (hs @ Wq^T + bq) * 0.125 -> g_q[h][s][d]  (R11-proven).
// CTA 1024 normalizes the block table and resets the fused-kernel barrier.
// -----------------------------------------------------------------------------
__global__ __launch_bounds__(256) void qproj_kernel(const float* __restrict__ hs,
                                                    const float* __restrict__ Wq,
                                                    const float* __restrict__ bq,
                                                    const int* __restrict__ bt_raw) {
    if (blockIdx.x == 1024) {
        if (threadIdx.x == 0) g_cnt = 0;   // reset spin barrier for this replay
        __shared__ int s_odd_nonzero;
        if (threadIdx.x == 0) s_odd_nonzero = 0;
        __syncthreads();
        int t = threadIdx.x;
        int w[8];
        int flag = 0;
#pragma unroll
        for (int k = 0; k < 8; k++) {
            w[k] = bt_raw[t * 8 + k];
            if ((k & 1) && w[k] != 0) flag = 1;
        }
        if (flag) atomicOr(&s_odd_nonzero, 1);
        __syncthreads();
        bool is32 = (s_odd_nonzero != 0);
        if (is32) {
#pragma unroll
            for (int k = 0; k < 8; k++) g_bt[t * 8 + k] = w[k] & 4095;
        } else {
#pragma unroll
            for (int k = 0; k < 4; k++) g_bt[t * 4 + k] = w[2 * k] & 4095;
#pragma unroll
            for (int k = 0; k < 4; k++)
                g_bt[1024 + t * 4 + k] = bt_raw[2048 + t * 8 + 2 * k] & 4095;
        }
        return;
    }

    int gw   = (blockIdx.x * 256 + threadIdx.x) >> 5;
    int lane = threadIdx.x & 31;
    int s = gw >> 9;
    int j = gw & 511;
    const float4* x = (const float4*)(hs + s * HIDDEN);
    const float4* w = (const float4*)(Wq + j * HIDDEN);
    float acc = 0.f;
#pragma unroll
    for (int it = 0; it < 4; it++) {
        float4 a = x[lane + it * 32];
        float4 b = w[lane + it * 32];
        acc += a.x * b.x + a.y * b.y + a.z * b.z + a.w * b.w;
    }
#pragma unroll
    for (int off = 16; off; off >>= 1) acc += __shfl_xor_sync(0xffffffffu, acc, off);
    if (lane == 0) {
        float v = (acc + bq[j]) * 0.125f;
        int h = j >> 6, d = j & 63;
        g_q[(h * QLEN + s) * HDIM + d] = v;
    }
}

// -----------------------------------------------------------------------------
// Kernel 2: split-KV attention. 64 threads, 4 q-rows/thread, 32-key tiles.
// K stored CHUNK-MAJOR (KT[chunk][key], unpadded, conflict-free column reads);
// V linear key-major; PS[gs][key] (conflict-free stores, broadcast reads).
// smem 38KB -> 6 CTAs/SM. grid (NSPLIT, NHEADS) = 1024 CTAs.
// -----------------------------------------------------------------------------
__global__ __launch_bounds__(64) void attn_kernel(const float* __restrict__ kc,
                                                  const float* __restrict__ vc) {
    const int h   = blockIdx.y;
    const int sp  = blockIdx.x;
    const int tid = threadIdx.x;
    const int col = tid & 15;
    const int gs  = tid >> 4;

    __shared__ __align__(16) float  QS[16 * 64];       // linear (row reads broadcast)
    __shared__ __align__(16) float  KS[2][32 * 64];    // chunk-major [chunk][key][4]
    __shared__ __align__(16) float  VS[2][32 * 64];    // linear key-major
    __shared__ __align__(16) float4 PS[4][32];         // [gs][key]

    // q tile -> smem
    {
        const float4* qg = (const float4*)(g_q + h * QLEN * HDIM);
        float4* qs = (float4*)QS;
#pragma unroll
        for (int j = 0; j < 4; j++) {
            int e = tid + j * 64;
            qs[e] = qg[e];
        }
    }

    uint32_t kbase0 = s2u(KS[0]), vbase0 = s2u(VS[0]);
    const uint32_t bufstep = 32 * 64 * 4;   // 8 KB
    // chunk-major K dst: element e (key r=e>>4, chunk c=e&15) -> (c*32 + r)*16 bytes
    uint32_t kdoffA[4];
#pragma unroll
    for (int j = 0; j < 4; j++) {
        int e = tid + j * 64;              // e in [0,256): block 0, keys 0..15
        kdoffA[j] = (uint32_t)((((e & 15) << 5) + (e >> 4)) << 4);
    }
    // block 1 keys 16..31: same chunk, key+16 -> +256 bytes

    const int lb0 = sp * BPS;
    const uint32_t headoff = (uint32_t)h * (BLKSZ * HDIM);

    // prologue: stage tile 0 (blocks lb0, lb0+1) into buffer 0
    {
        uint32_t b0 = (uint32_t)g_bt[lb0], b1 = (uint32_t)g_bt[lb0 + 1];
        const float* kb0 = kc + (size_t)b0 * (NHEADS * BLKSZ * HDIM) + headoff;
        const float* kb1 = kc + (size_t)b1 * (NHEADS * BLKSZ * HDIM) + headoff;
        const float* vb0 = vc + (size_t)b0 * (NHEADS * BLKSZ * HDIM) + headoff;
        const float* vb1 = vc + (size_t)b1 * (NHEADS * BLKSZ * HDIM) + headoff;
#pragma unroll
        for (int j = 0; j < 4; j++) {
            int e = tid + j * 64;
            cpa16(kbase0 + kdoffA[j],       kb0 + e * 4);
            cpa16(kbase0 + kdoffA[j] + 256, kb1 + e * 4);
            cpa16(vbase0 + (uint32_t)e * 16,         vb0 + e * 4);
            cpa16(vbase0 + (uint32_t)(e + 256) * 16, vb1 + e * 4);
        }
        cpa_commit();
    }

    ull l01 = 0, l23 = 0;
    ull oxy[4] = {0, 0, 0, 0}, ozw[4] = {0, 0, 0, 0};
    const ull ONE2 = pk2(1.f, 1.f);

    const ulonglong2* qp0 = (const ulonglong2*)(QS + (gs * 4 + 0) * 64);
    const ulonglong2* qp1 = (const ulonglong2*)(QS + (gs * 4 + 1) * 64);
    const ulonglong2* qp2 = (const ulonglong2*)(QS + (gs * 4 + 2) * 64);
    const ulonglong2* qp3 = (const ulonglong2*)(QS + (gs * 4 + 3) * 64);

    for (int it = 0; it < ITERS; it++) {
        const int cur = it & 1;
        cpa_wait0();
        __syncthreads();

        if (it + 1 < ITERS) {
            uint32_t b0 = (uint32_t)g_bt[lb0 + 2 * it + 2];
            uint32_t b1 = (uint32_t)g_bt[lb0 + 2 * it + 3];
            const float* kb0 = kc + (size_t)b0 * (NHEADS * BLKSZ * HDIM) + headoff;
            const float* kb1 = kc + (size_t)b1 * (NHEADS * BLKSZ * HDIM) + headoff;
            const float* vb0 = vc + (size_t)b0 * (NHEADS * BLKSZ * HDIM) + headoff;
            const float* vb1 = vc + (size_t)b1 * (NHEADS * BLKSZ * HDIM) + headoff;
            uint32_t kdst = kbase0 + (cur ^ 1) * bufstep;
            uint32_t vdst = vbase0 + (cur ^ 1) * bufstep;
#pragma unroll
            for (int j = 0; j < 4; j++) {
                int e = tid + j * 64;
                cpa16(kdst + kdoffA[j],       kb0 + e * 4);
                cpa16(kdst + kdoffA[j] + 256, kb1 + e * 4);
                cpa16(vdst + (uint32_t)e * 16,         vb0 + e * 4);
                cpa16(vdst + (uint32_t)(e + 256) * 16, vb1 + e * 4);
            }
            cpa_commit();
        }

        // ---- scores: 4 rows x keys {col, col+16} (chunk-major K)
        const float* ksb = KS[cur];
        ull A0 = 0, B0 = 0, A1 = 0, B1 = 0, A2 = 0, B2 = 0, A3 = 0, B3 = 0;
        ull C0 = 0, D0 = 0, C1 = 0, D1 = 0, C2 = 0, D2 = 0, C3 = 0, D3 = 0;
#pragma unroll
        for (int i = 0; i < 16; i++) {
            // chunk i: 32 keys x 16B at ksb + i*128 floats; key col at +col*4 floats
            ulonglong2 ka = *(const ulonglong2*)(ksb + i * 128 + col * 4);
            ulonglong2 kb = *(const ulonglong2*)(ksb + i * 128 + col * 4 + 64);
            ulonglong2 q0 = qp0[i], q1 = qp1[i], q2 = qp2[i], q3 = qp3[i];
            A0 = fma2(q0.x, ka.x, A0); B0 = fma2(q0.y, ka.y, B0);
            A1 = fma2(q1.x, ka.x, A1); B1 = fma2(q1.y, ka.y, B1);
            A2 = fma2(q2.x, ka.x, A2); B2 = fma2(q2.y, ka.y, B2);
            A3 = fma2(q3.x, ka.x, A3); B3 = fma2(q3.y, ka.y, B3);
            C0 = fma2(q0.x, kb.x, C0); D0 = fma2(q0.y, kb.y, D0);
            C1 = fma2(q1.x, kb.x, C1); D1 = fma2(q1.y, kb.y, D1);
            C2 = fma2(q2.x, kb.x, C2); D2 = fma2(q2.y, kb.y, D2);
            C3 = fma2(q3.x, kb.x, C3); D3 = fma2(q3.y, kb.y, D3);
        }
        {
            float x, y, z, w;
            float pa0, pa1, pa2, pa3, pb0, pb1, pb2, pb3;
            upk2(A0, x, y); upk2(B0, z, w); pa0 = __expf((x + y) + (z + w));
            upk2(A1, x, y); upk2(B1, z, w); pa1 = __expf((x + y) + (z + w));
            upk2(A2, x, y); upk2(B2, z, w); pa2 = __expf((x + y) + (z + w));
            upk2(A3, x, y); upk2(B3, z, w); pa3 = __expf((x + y) + (z + w));
            upk2(C0, x, y); upk2(D0, z, w); pb0 = __expf((x + y) + (z + w));
            upk2(C1, x, y); upk2(D1, z, w); pb1 = __expf((x + y) + (z + w));
            upk2(C2, x, y); upk2(D2, z, w); pb2 = __expf((x + y) + (z + w));
            upk2(C3, x, y); upk2(D3, z, w); pb3 = __expf((x + y) + (z + w));
            PS[gs][col]      = make_float4(pa0, pa1, pa2, pa3);   // contiguous store
            PS[gs][col + 16] = make_float4(pb0, pb1, pb2, pb3);
        }
        __syncwarp();   // PS[gs][*] produced & consumed by the same 16-lane groups

        // ---- PV + l: 4 rows x d-quad 'col', 32 keys (linear V; PS broadcast)
        const float* vbase = VS[cur];
#pragma unroll
        for (int k2 = 0; k2 < 32; k2++) {
            ulonglong2 v2  = ((const ulonglong2*)(vbase + k2 * 64))[col];
            ulonglong2 pf2 = *((const ulonglong2*)&PS[gs][k2]);
            l01 = fma2(pf2.x, ONE2, l01);
            l23 = fma2(pf2.y, ONE2, l23);
            float pa, pb, pc, pd;
            upk2(pf2.x, pa, pb); upk2(pf2.y, pc, pd);
            ull pp0 = pk2(pa, pa), pp1 = pk2(pb, pb);
            ull pp2 = pk2(pc, pc), pp3 = pk2(pd, pd);
            oxy[0] = fma2(pp0, v2.x, oxy[0]); ozw[0] = fma2(pp0, v2.y, ozw[0]);
            oxy[1] = fma2(pp1, v2.x, oxy[1]); ozw[1] = fma2(pp1, v2.y, ozw[1]);
            oxy[2] = fma2(pp2, v2.x, oxy[2]); ozw[2] = fma2(pp2, v2.y, ozw[2]);
            oxy[3] = fma2(pp3, v2.x, oxy[3]); ozw[3] = fma2(pp3, v2.y, ozw[3]);
        }
    }

    // write unnormalized partials (rows gs*4+j)
#pragma unroll
    for (int j = 0; j < 4; j++) {
        float4 o;
        upk2(oxy[j], o.x, o.y); upk2(ozw[j], o.z, o.w);
        ((float4*)(g_po + ((h * NSPLIT + sp) * QLEN + gs * 4 + j) * HDIM))[col] = o;
    }
    if (col == 0) {
        float la, lb, lc, ld;
        upk2(l01, la, lb); upk2(l23, lc, ld);
        g_pl[(h * NSPLIT + sp) * QLEN + gs * 4 + 0] = la;
        g_pl[(h * NSPLIT + sp) * QLEN + gs * 4 + 1] = lb;
        g_pl[(h * NSPLIT + sp) * QLEN + gs * 4 + 2] = lc;
        g_pl[(h * NSPLIT + sp) * QLEN + gs * 4 + 3] = ld;
    }
}

// -----------------------------------------------------------------------------
// Kernel 3 (fused): reduce over 128 splits + out-projection (R11 version).
// 128 CTAs x 1024 threads, global spin barrier between stages.
// -----------------------------------------------------------------------------
__global__ __launch_bounds__(1024) void fused_tail_kernel(const float* __restrict__ Wo,
                                                          const float* __restrict__ bo,
                                                          float* __restrict__ out) {
    const int bid = blockIdx.x;
    const int h = bid >> 4, qi = bid & 15;
    const int t = threadIdx.x;
    const int jbase = bid * 4;

    __shared__ float4 pacc[64][16];
    __shared__ float4 pacc2[16][16];
    __shared__ float  lpart[4];
    __shared__ __align__(16) float WS[4][HIDDEN];
    __shared__ __align__(16) float AS[QLEN * HIDDEN];

    // stage 0: async prefetch of Wo rows
    if (t < 512) {
        int row = t >> 7, chunk = t & 127;
        cpa16(s2u(&WS[row][chunk * 4]), Wo + (size_t)(jbase + row) * HIDDEN + chunk * 4);
    }
    cpa_commit();

    // stage 1: reduce over 128 splits (2 per chunk-thread)
    int q4 = t & 15, ch = t >> 4;
    const float4* src = (const float4*)g_po;
    float4 a0, a1;
    {
        long long base = ((long long)(h * NSPLIT + ch * 2) * QLEN + qi) * (HDIM / 4) + q4;
        const long long step = (long long)QLEN * (HDIM / 4);
        a0 = src[base];
        a1 = src[base + step];
    }
    float4 acc;
    acc.x = a0.x + a1.x; acc.y = a0.y + a1.y;
    acc.z = a0.z + a1.z; acc.w = a0.w + a1.w;
    pacc[ch][q4] = acc;

    if (t < NSPLIT) {
        float v = g_pl[(h * NSPLIT + t) * QLEN + qi];
#pragma unroll
        for (int off = 16; off; off >>= 1) v += __shfl_xor_sync(0xffffffffu, v, off);
        if ((t & 31) == 0) lpart[t >> 5] = v;
    }
    __syncthreads();

    if (t < 256) {
        int g = t >> 4;
        float4 s0 = pacc[g * 4 + 0][q4], s1 = pacc[g * 4 + 1][q4];
        float4 s2 = pacc[g * 4 + 2][q4], s3 = pacc[g * 4 + 3][q4];
        float4 s;
        s.x = (s0.x + s1.x) + (s2.x + s3.x);
        s.y = (s0.y + s1.y) + (s2.y + s3.y);
        s.z = (s0.z + s1.z) + (s2.z + s3.z);
        s.w = (s0.w + s1.w) + (s2.w + s3.w);
        pacc2[g][q4] = s;
    }
    __syncthreads();

    if (t < 16) {
        float4 s = make_float4(0.f, 0.f, 0.f, 0.f);
#pragma unroll
        for (int g = 0; g < 16; g++) {
            float4 v = pacc2[g][t];
            s.x += v.x; s.y += v.y; s.z += v.z; s.w += v.w;
        }
        float L = lpart[0] + lpart[1] + lpart[2] + lpart[3];
        float inv = 1.f / L;
        s.x *= inv; s.y *= inv; s.z *= inv; s.w *= inv;
        ((float4*)(g_ao + qi * HIDDEN + h * HDIM))[t] = s;
    }
    __syncthreads();

    // global barrier
    if (t == 0) {
        __threadfence();
        atomicAdd(&g_cnt, 1);
        while (atomicAdd(&g_cnt, 0) < 128) { __nanosleep(64); }
    }
    __syncthreads();
    __threadfence();

    // stage 2: oproj (64 outputs per CTA, warp-per-output)
    {
        const float4* ag = (const float4*)g_ao;
        float4* asp = (float4*)AS;
#pragma unroll
        for (int j = 0; j < 2; j++) asp[t + j * 1024] = ag[t + j * 1024];
    }
    cpa_wait0();
    __syncthreads();

    int w = t >> 5, lane = t & 31;
#pragma unroll
    for (int r = 0; r < 2; r++) {
        int o  = r * 32 + w;
        int s  = o & 15;
        int jj = o >> 4;
        const float4* x = (const float4*)(AS + s * HIDDEN);
        const float4* ww = (const float4*)(WS[jj]);
        float acc2 = 0.f;
#pragma unroll
        for (int it = 0; it < 4; it++) {
            float4 a = x[lane + it * 32];
            float4 b = ww[lane + it * 32];
            acc2 += a.x * b.x + a.y * b.y + a.z * b.z + a.w * b.w;
        }
#pragma unroll
        for (int off = 16; off; off >>= 1) acc2 += __shfl_xor_sync(0xffffffffu, acc2, off);
        if (lane == 0) out[s * HIDDEN + jbase + jj] = acc2 + bo[jbase + jj];
    }
}

// -----------------------------------------------------------------------------
extern "C" void kernel_launch(void* const* d_in, const int* in_sizes, int n_in,
                              void* d_out, int out_size) {
    const float *hs = 0, *kc = 0, *vc = 0, *Wq = 0, *bq = 0, *Wo = 0, *bo = 0;
    const int* bt_raw = 0;
    for (int i = 0; i < n_in; i++) {
        switch (in_sizes[i]) {
            case QLEN * HIDDEN:                 hs = (const float*)d_in[i]; break;
            case 4096 * NHEADS * BLKSZ * HDIM:
                if (!kc) kc = (const float*)d_in[i];
                else     vc = (const float*)d_in[i];
                break;
            case HIDDEN * HIDDEN:
                if (!Wq) Wq = (const float*)d_in[i];
                else     Wo = (const float*)d_in[i];
                break;
            case HIDDEN:
                if (!bq) bq = (const float*)d_in[i];
                else     bo = (const float*)d_in[i];
                break;
            case NLOGICAL:                      bt_raw = (const int*)d_in[i]; break;
            default: break;
        }
    }
    float* out = (float*)d_out;

    qproj_kernel<<<1025, 256>>>(hs, Wq, bq, bt_raw);  // CTA 1024 = btnorm + barrier reset
    dim3 g(NSPLIT, NHEADS);
    attn_kernel<<<g, 64>>>(kc, vc);
    fused_tail_kernel<<<128, 1024>>>(Wo, bo, out);
}

// round 15
// speedup vs baseline: 1.1442x; 1.1442x over previous
#include <cuda_runtime.h>
#include <cstdint>

#define NHEADS 8
#define HDIM   64
#define QLEN   16
#define HIDDEN 512
#define BLKSZ  16
#define NLOGICAL 2048
#define NSPLIT 128
#define BPS (NLOGICAL / NSPLIT)   // 16 blocks per split
#define ITERS (BPS / 2)           // 8 iterations of 32 keys

typedef unsigned long long ull;

// scratch (no cudaMalloc allowed)
__device__ __align__(16) float g_q [NHEADS * QLEN * HDIM];
__device__ __align__(16) float g_pl[NHEADS * NSPLIT * QLEN];
__device__ __align__(16) float g_po[NHEADS * NSPLIT * QLEN * HDIM];
__device__ __align__(16) float g_ao[QLEN * HIDDEN];
__device__ int g_bt[NLOGICAL];

// ---- packed f32x2 helpers --------------------------------------------------
__device__ __forceinline__ ull pk2(float lo, float hi) {
    ull r; asm("mov.b64 %0,{%1,%2};" : "=l"(r) : "f"(lo), "f"(hi)); return r;
}
__device__ __forceinline__ void upk2(ull p, float& lo, float& hi) {
    asm("mov.b64 {%0,%1},%2;" : "=f"(lo), "=f"(hi) : "l"(p));
}
__device__ __forceinline__ ull fma2(ull a, ull b, ull c) {
    ull d; asm("fma.rn.f32x2 %0,%1,%2,%3;" : "=l"(d) : "l"(a), "l"(b), "l"(c)); return d;
}

// ---- cp.async helpers --------------------------------------------------------
__device__ __forceinline__ uint32_t s2u(const void* p) {
    uint32_t a;
    asm("{ .reg .u64 t; cvta.to.shared.u64 t, %1; cvt.u32.u64 %0, t; }" : "=r"(a) : "l"(p));
    return a;
}
__device__ __forceinline__ void cpa16(uint32_t dst, const void* src) {
    asm volatile("cp.async.cg.shared.global [%0], [%1], 16;" :: "r"(dst), "l"(src) : "memory");
}
__device__ __forceinline__ void cpa_commit() {
    asm volatile("cp.async.commit_group;" ::: "memory");
}
__device__ __forceinline__ void cpa_wait0() {
    asm volatile("cp.async.wait_group 0;" ::: "memory");
}

// -----------------------------------------------------------------------------
// Kernel 1: q = (hs @ Wq^T + bq) * 0.125 -> g_q[h][s][d]  (R11-proven).
// CTA 1024 normalizes the block table.
// -----------------------------------------------------------------------------
__global__ __launch_bounds__(256) void qproj_kernel(const float* __restrict__ hs,
                                                    const float* __restrict__ Wq,
                                                    const float* __restrict__ bq,
                                                    const int* __restrict__ bt_raw) {
    if (blockIdx.x == 1024) {
        __shared__ int s_odd_nonzero;
        if (threadIdx.x == 0) s_odd_nonzero = 0;
        __syncthreads();
        int t = threadIdx.x;
        int w[8];
        int flag = 0;
#pragma unroll
        for (int k = 0; k < 8; k++) {
            w[k] = bt_raw[t * 8 + k];
            if ((k & 1) && w[k] != 0) flag = 1;
        }
        if (flag) atomicOr(&s_odd_nonzero, 1);
        __syncthreads();
        bool is32 = (s_odd_nonzero != 0);
        if (is32) {
#pragma unroll
            for (int k = 0; k < 8; k++) g_bt[t * 8 + k] = w[k] & 4095;
        } else {
#pragma unroll
            for (int k = 0; k < 4; k++) g_bt[t * 4 + k] = w[2 * k] & 4095;
#pragma unroll
            for (int k = 0; k < 4; k++)
                g_bt[1024 + t * 4 + k] = bt_raw[2048 + t * 8 + 2 * k] & 4095;
        }
        return;
    }

    int gw   = (blockIdx.x * 256 + threadIdx.x) >> 5;
    int lane = threadIdx.x & 31;
    int s = gw >> 9;
    int j = gw & 511;
    const float4* x = (const float4*)(hs + s * HIDDEN);
    const float4* w = (const float4*)(Wq + j * HIDDEN);
    float acc = 0.f;
#pragma unroll
    for (int it = 0; it < 4; it++) {
        float4 a = x[lane + it * 32];
        float4 b = w[lane + it * 32];
        acc += a.x * b.x + a.y * b.y + a.z * b.z + a.w * b.w;
    }
#pragma unroll
    for (int off = 16; off; off >>= 1) acc += __shfl_xor_sync(0xffffffffu, acc, off);
    if (lane == 0) {
        float v = (acc + bq[j]) * 0.125f;
        int h = j >> 6, d = j & 63;
        g_q[(h * QLEN + s) * HDIM + d] = v;
    }
}

// -----------------------------------------------------------------------------
// Kernel 2: split-KV attention (exact R10/R11 winner). 64 threads,
// 4 q-rows/thread, 32-key tiles, K pad-68, V linear, cp.async staging.
// grid (NSPLIT, NHEADS) = 1024 CTAs.
// -----------------------------------------------------------------------------
__global__ __launch_bounds__(64) void attn_kernel(const float* __restrict__ kc,
                                                  const float* __restrict__ vc) {
    const int h   = blockIdx.y;
    const int sp  = blockIdx.x;
    const int tid = threadIdx.x;
    const int col = tid & 15;
    const int gs  = tid >> 4;

    __shared__ __align__(16) float  QS[16 * 68];
    __shared__ __align__(16) float  KS[2][32 * 68];
    __shared__ __align__(16) float  VS[2][32 * 64];
    __shared__ __align__(16) float4 PS[32][4];

    {
        const float4* qg = (const float4*)(g_q + h * QLEN * HDIM);
#pragma unroll
        for (int j = 0; j < 4; j++) {
            int e = tid + j * 64;
            ((float4*)(QS + (e >> 4) * 68))[e & 15] = qg[e];
        }
    }

    uint32_t kbase0 = s2u(KS[0]), vbase0 = s2u(VS[0]);
    const uint32_t kstep = 32 * 68 * 4, vstep = 32 * 64 * 4;
    uint32_t kdoff[8];
#pragma unroll
    for (int j = 0; j < 8; j++) {
        int e = tid + j * 64;
        kdoff[j] = (uint32_t)((e >> 4) * 68 * 4 + (e & 15) * 16);
    }

    const int lb0 = sp * BPS;
    const uint32_t headoff = (uint32_t)h * (BLKSZ * HDIM);

    {
        uint32_t b0 = (uint32_t)g_bt[lb0], b1 = (uint32_t)g_bt[lb0 + 1];
        const float* kb0 = kc + (size_t)b0 * (NHEADS * BLKSZ * HDIM) + headoff;
        const float* kb1 = kc + (size_t)b1 * (NHEADS * BLKSZ * HDIM) + headoff;
        const float* vb0 = vc + (size_t)b0 * (NHEADS * BLKSZ * HDIM) + headoff;
        const float* vb1 = vc + (size_t)b1 * (NHEADS * BLKSZ * HDIM) + headoff;
#pragma unroll
        for (int j = 0; j < 4; j++) {
            int e = tid + j * 64;
            cpa16(kbase0 + kdoff[j],     kb0 + e * 4);
            cpa16(kbase0 + kdoff[j + 4], kb1 + e * 4);
            cpa16(vbase0 + (uint32_t)e * 16,         vb0 + e * 4);
            cpa16(vbase0 + (uint32_t)(e + 256) * 16, vb1 + e * 4);
        }
        cpa_commit();
    }

    ull l01 = 0, l23 = 0;
    ull oxy[4] = {0, 0, 0, 0}, ozw[4] = {0, 0, 0, 0};
    const ull ONE2 = pk2(1.f, 1.f);

    const ulonglong2* qp0 = (const ulonglong2*)(QS + (gs * 4 + 0) * 68);
    const ulonglong2* qp1 = (const ulonglong2*)(QS + (gs * 4 + 1) * 68);
    const ulonglong2* qp2 = (const ulonglong2*)(QS + (gs * 4 + 2) * 68);
    const ulonglong2* qp3 = (const ulonglong2*)(QS + (gs * 4 + 3) * 68);

    for (int it = 0; it < ITERS; it++) {
        const int cur = it & 1;
        cpa_wait0();
        __syncthreads();

        if (it + 1 < ITERS) {
            uint32_t b0 = (uint32_t)g_bt[lb0 + 2 * it + 2];
            uint32_t b1 = (uint32_t)g_bt[lb0 + 2 * it + 3];
            const float* kb0 = kc + (size_t)b0 * (NHEADS * BLKSZ * HDIM) + headoff;
            const float* kb1 = kc + (size_t)b1 * (NHEADS * BLKSZ * HDIM) + headoff;
            const float* vb0 = vc + (size_t)b0 * (NHEADS * BLKSZ * HDIM) + headoff;
            const float* vb1 = vc + (size_t)b1 * (NHEADS * BLKSZ * HDIM) + headoff;
            uint32_t kdst = kbase0 + (cur ^ 1) * kstep;
            uint32_t vdst = vbase0 + (cur ^ 1) * vstep;
#pragma unroll
            for (int j = 0; j < 4; j++) {
                int e = tid + j * 64;
                cpa16(kdst + kdoff[j],     kb0 + e * 4);
                cpa16(kdst + kdoff[j + 4], kb1 + e * 4);
                cpa16(vdst + (uint32_t)e * 16,         vb0 + e * 4);
                cpa16(vdst + (uint32_t)(e + 256) * 16, vb1 + e * 4);
            }
            cpa_commit();
        }

        // ---- scores: 4 rows x keys {col, col+16}
        const ulonglong2* kpA = (const ulonglong2*)(KS[cur] + col * 68);
        const ulonglong2* kpB = (const ulonglong2*)(KS[cur] + (col + 16) * 68);
        ull A0 = 0, B0 = 0, A1 = 0, B1 = 0, A2 = 0, B2 = 0, A3 = 0, B3 = 0;
        ull C0 = 0, D0 = 0, C1 = 0, D1 = 0, C2 = 0, D2 = 0, C3 = 0, D3 = 0;
#pragma unroll
        for (int i = 0; i < 16; i++) {
            ulonglong2 ka = kpA[i], kb = kpB[i];
            ulonglong2 q0 = qp0[i], q1 = qp1[i], q2 = qp2[i], q3 = qp3[i];
            A0 = fma2(q0.x, ka.x, A0); B0 = fma2(q0.y, ka.y, B0);
            A1 = fma2(q1.x, ka.x, A1); B1 = fma2(q1.y, ka.y, B1);
            A2 = fma2(q2.x, ka.x, A2); B2 = fma2(q2.y, ka.y, B2);
            A3 = fma2(q3.x, ka.x, A3); B3 = fma2(q3.y, ka.y, B3);
            C0 = fma2(q0.x, kb.x, C0); D0 = fma2(q0.y, kb.y, D0);
            C1 = fma2(q1.x, kb.x, C1); D1 = fma2(q1.y, kb.y, D1);
            C2 = fma2(q2.x, kb.x, C2); D2 = fma2(q2.y, kb.y, D2);
            C3 = fma2(q3.x, kb.x, C3); D3 = fma2(q3.y, kb.y, D3);
        }
        {
            float x, y, z, w;
            float pa0, pa1, pa2, pa3, pb0, pb1, pb2, pb3;
            upk2(A0, x, y); upk2(B0, z, w); pa0 = __expf((x + y) + (z + w));
            upk2(A1, x, y); upk2(B1, z, w); pa1 = __expf((x + y) + (z + w));
            upk2(A2, x, y); upk2(B2, z, w); pa2 = __expf((x + y) + (z + w));
            upk2(A3, x, y); upk2(B3, z, w); pa3 = __expf((x + y) + (z + w));
            upk2(C0, x, y); upk2(D0, z, w); pb0 = __expf((x + y) + (z + w));
            upk2(C1, x, y); upk2(D1, z, w); pb1 = __expf((x + y) + (z + w));
            upk2(C2, x, y); upk2(D2, z, w); pb2 = __expf((x + y) + (z + w));
            upk2(C3, x, y); upk2(D3, z, w); pb3 = __expf((x + y) + (z + w));
            PS[col][gs]      = make_float4(pa0, pa1, pa2, pa3);
            PS[col + 16][gs] = make_float4(pb0, pb1, pb2, pb3);
        }
        __syncwarp();

        // ---- PV + l: 4 rows x d-quad 'col', 32 keys (linear V)
        const float* vbase = VS[cur];
#pragma unroll
        for (int k2 = 0; k2 < 32; k2++) {
            ulonglong2 v2  = ((const ulonglong2*)(vbase + k2 * 64))[col];
            ulonglong2 pf2 = *((const ulonglong2*)&PS[k2][gs]);
            l01 = fma2(pf2.x, ONE2, l01);
            l23 = fma2(pf2.y, ONE2, l23);
            float pa, pb, pc, pd;
            upk2(pf2.x, pa, pb); upk2(pf2.y, pc, pd);
            ull pp0 = pk2(pa, pa), pp1 = pk2(pb, pb);
            ull pp2 = pk2(pc, pc), pp3 = pk2(pd, pd);
            oxy[0] = fma2(pp0, v2.x, oxy[0]); ozw[0] = fma2(pp0, v2.y, ozw[0]);
            oxy[1] = fma2(pp1, v2.x, oxy[1]); ozw[1] = fma2(pp1, v2.y, ozw[1]);
            oxy[2] = fma2(pp2, v2.x, oxy[2]); ozw[2] = fma2(pp2, v2.y, ozw[2]);
            oxy[3] = fma2(pp3, v2.x, oxy[3]); ozw[3] = fma2(pp3, v2.y, ozw[3]);
        }
    }

#pragma unroll
    for (int j = 0; j < 4; j++) {
        float4 o;
        upk2(oxy[j], o.x, o.y); upk2(ozw[j], o.z, o.w);
        ((float4*)(g_po + ((h * NSPLIT + sp) * QLEN + gs * 4 + j) * HDIM))[col] = o;
    }
    if (col == 0) {
        float la, lb, lc, ld;
        upk2(l01, la, lb); upk2(l23, lc, ld);
        g_pl[(h * NSPLIT + sp) * QLEN + gs * 4 + 0] = la;
        g_pl[(h * NSPLIT + sp) * QLEN + gs * 4 + 1] = lb;
        g_pl[(h * NSPLIT + sp) * QLEN + gs * 4 + 2] = lc;
        g_pl[(h * NSPLIT + sp) * QLEN + gs * 4 + 3] = ld;
    }
}

// -----------------------------------------------------------------------------
// Kernel 3: additive combine over 128 splits, 512 CTAs (4x d-split per (h,qi)).
// CTA = (h, qi, dc); 256 threads. Each CTA reduces a 16-float d-chunk.
// -----------------------------------------------------------------------------
__global__ __launch_bounds__(256) void reduce_kernel() {
    const int bid = blockIdx.x;
    const int hq = bid >> 2;            // 0..127
    const int h = hq >> 4, qi = hq & 15;
    const int dc = bid & 3;             // d-chunk: q4 in [4dc, 4dc+4)
    const int t = threadIdx.x;

    __shared__ float4 pacc[64][4];
    __shared__ float4 pacc2[16][4];
    __shared__ float  Lsh;

    int q4l = t & 3, ch = t >> 2;       // ch 0..63, 2 splits each
    int q4 = dc * 4 + q4l;
    const float4* src = (const float4*)g_po;
    float4 a0, a1;
    {
        long long base = ((long long)(h * NSPLIT + ch * 2) * QLEN + qi) * (HDIM / 4) + q4;
        const long long step = (long long)QLEN * (HDIM / 4);
        a0 = src[base];
        a1 = src[base + step];
    }
    float4 acc;
    acc.x = a0.x + a1.x; acc.y = a0.y + a1.y;
    acc.z = a0.z + a1.z; acc.w = a0.w + a1.w;
    pacc[ch][q4l] = acc;

    // L: warp 0 sums the 128 g_pl entries (redundant across the 4 dc-CTAs; cheap)
    if (t < 32) {
        float v = 0.f;
#pragma unroll
        for (int k = 0; k < 4; k++)
            v += g_pl[(h * NSPLIT + t * 4 + k) * QLEN + qi];
#pragma unroll
        for (int off = 16; off; off >>= 1) v += __shfl_xor_sync(0xffffffffu, v, off);
        if (t == 0) Lsh = v;
    }
    __syncthreads();

    if (t < 64) {
        int g = t >> 2, q = t & 3;
        float4 s0 = pacc[g * 4 + 0][q], s1 = pacc[g * 4 + 1][q];
        float4 s2 = pacc[g * 4 + 2][q], s3 = pacc[g * 4 + 3][q];
        float4 s;
        s.x = (s0.x + s1.x) + (s2.x + s3.x);
        s.y = (s0.y + s1.y) + (s2.y + s3.y);
        s.z = (s0.z + s1.z) + (s2.z + s3.z);
        s.w = (s0.w + s1.w) + (s2.w + s3.w);
        pacc2[g][q] = s;
    }
    __syncthreads();

    if (t < 4) {
        float4 s = make_float4(0.f, 0.f, 0.f, 0.f);
#pragma unroll
        for (int g = 0; g < 16; g++) {
            float4 v = pacc2[g][t];
            s.x += v.x; s.y += v.y; s.z += v.z; s.w += v.w;
        }
        float inv = 1.f / Lsh;
        s.x *= inv; s.y *= inv; s.z *= inv; s.w *= inv;
        ((float4*)(g_ao + qi * HIDDEN + h * HDIM))[dc * 4 + t] = s;
    }
}

// -----------------------------------------------------------------------------
// Kernel 4: out = g_ao @ Wo^T + bo (exact R10 warp-per-output version)
// -----------------------------------------------------------------------------
__global__ __launch_bounds__(256) void oproj_kernel(const float* __restrict__ Wo,
                                                    const float* __restrict__ bo,
                                                    float* __restrict__ out) {
    int gw   = (blockIdx.x * 256 + threadIdx.x) >> 5;
    int lane = threadIdx.x & 31;
    int s = gw >> 9;
    int j = gw & 511;
    const float4* x = (const float4*)(g_ao + s * HIDDEN);
    const float4* w = (const float4*)(Wo + j * HIDDEN);
    float acc = 0.f;
#pragma unroll
    for (int it = 0; it < 4; it++) {
        float4 a = x[lane + it * 32];
        float4 b = w[lane + it * 32];
        acc += a.x * b.x + a.y * b.y + a.z * b.z + a.w * b.w;
    }
#pragma unroll
    for (int off = 16; off; off >>= 1) acc += __shfl_xor_sync(0xffffffffu, acc, off);
    if (lane == 0) out[s * HIDDEN + j] = acc + bo[j];
}

// -----------------------------------------------------------------------------
extern "C" void kernel_launch(void* const* d_in, const int* in_sizes, int n_in,
                              void* d_out, int out_size) {
    const float *hs = 0, *kc = 0, *vc = 0, *Wq = 0, *bq = 0, *Wo = 0, *bo = 0;
    const int* bt_raw = 0;
    for (int i = 0; i < n_in; i++) {
        switch (in_sizes[i]) {
            case QLEN * HIDDEN:                 hs = (const float*)d_in[i]; break;
            case 4096 * NHEADS * BLKSZ * HDIM:
                if (!kc) kc = (const float*)d_in[i];
                else     vc = (const float*)d_in[i];
                break;
            case HIDDEN * HIDDEN:
                if (!Wq) Wq = (const float*)d_in[i];
                else     Wo = (const float*)d_in[i];
                break;
            case HIDDEN:
                if (!bq) bq = (const float*)d_in[i];
                else     bo = (const float*)d_in[i];
                break;
            case NLOGICAL:                      bt_raw = (const int*)d_in[i]; break;
            default: break;
        }
    }
    float* out = (float*)d_out;

    qproj_kernel<<<1025, 256>>>(hs, Wq, bq, bt_raw);  // CTA 1024 = btnorm
    dim3 g(NSPLIT, NHEADS);
    attn_kernel<<<g, 64>>>(kc, vc);
    reduce_kernel<<<512, 256>>>();
    oproj_kernel<<<1024, 256>>>(Wo, bo, out);
}